// round 3
// baseline (speedup 1.0000x reference)
#include <cuda_runtime.h>
#include <cstdint>

#define HH 8
#define DD 1024
#define SS 1024
#define MIDD 2048
#define SOUT 512

typedef long long ll;

// ---------------- scratch (device globals; no allocation allowed) ----------
__device__ float g_qkv[3ll * DD * SS];          // 12 MB (block1 qkv; slot0 reused for q2)
__device__ float g_z[(ll)HH * DD * MIDD];       // 64 MB
__device__ float g_s[(ll)HH * 3 * DD * SS];     // 96 MB
__device__ float g_bm[(ll)HH * SS * SS];        // 32 MB
__device__ float g_att[(ll)HH * DD * SS];       // 32 MB
__device__ float g_y[(ll)SS * MIDD];            // 8 MB
__device__ float g_m[(ll)DD * SS];              // 4 MB
__device__ float g_h[(ll)DD * SS];              // 4 MB
__device__ float g_x1[(ll)DD * MIDD];           // 8 MB
__device__ float g_x2[(ll)DD * SOUT];           // 2 MB

// ---------------- generic batched SGEMM ------------------------------------
// C[M,N] = act(op(A)) @ act(op(B)), row-major.
//   TA: A stored as (K,M) instead of (M,K). TB: B stored as (N,K) instead of (K,N).
//   RA/RB: apply ReLU to operand elements at load. TH: tanh epilogue.
// All M,N multiples of 128; all K multiples of 8 (and 4 for float4 loads).

#define BM 128
#define BN 128
#define BK 8

__device__ __forceinline__ float4 relu4(float4 v) {
    v.x = fmaxf(v.x, 0.f); v.y = fmaxf(v.y, 0.f);
    v.z = fmaxf(v.z, 0.f); v.w = fmaxf(v.w, 0.f);
    return v;
}

template<bool TA, bool TB, bool RA, bool RB, bool TH>
__global__ __launch_bounds__(256) void gemm_k(
    const float* __restrict__ Ag, const float* __restrict__ Bg, float* __restrict__ Cg,
    int M, int N, int K, ll sA, ll sB, ll sC)
{
    const float* A = Ag + (ll)blockIdx.z * sA;
    const float* B = Bg + (ll)blockIdx.z * sB;
    float*       C = Cg + (ll)blockIdx.z * sC;
    const int m0 = blockIdx.y * BM;
    const int n0 = blockIdx.x * BN;

    __shared__ __align__(16) float As[BK][BM];
    __shared__ __align__(16) float Bs[BK][BN];

    const int tid = threadIdx.x;        // 0..255
    const int tx  = tid & 15;
    const int ty  = tid >> 4;

    float acc[8][8] = {};

    for (int k0 = 0; k0 < K; k0 += BK) {
        float4 av, bv;
        int am, ak, bn, bk;
        if (!TA) {                       // A (M,K): float4 along K
            am = tid >> 1; ak = (tid & 1) * 4;
            av = *(const float4*)(A + (ll)(m0 + am) * K + k0 + ak);
        } else {                         // A (K,M): float4 along M
            ak = tid >> 5; am = (tid & 31) * 4;
            av = *(const float4*)(A + (ll)(k0 + ak) * M + m0 + am);
        }
        if (RA) av = relu4(av);
        if (!TB) {                       // B (K,N): float4 along N
            bk = tid >> 5; bn = (tid & 31) * 4;
            bv = *(const float4*)(B + (ll)(k0 + bk) * N + n0 + bn);
        } else {                         // B (N,K): float4 along K
            bn = tid >> 1; bk = (tid & 1) * 4;
            bv = *(const float4*)(B + (ll)(n0 + bn) * K + k0 + bk);
        }
        if (RB) bv = relu4(bv);

        if (!TA) {
            As[ak + 0][am] = av.x; As[ak + 1][am] = av.y;
            As[ak + 2][am] = av.z; As[ak + 3][am] = av.w;
        } else {
            *(float4*)&As[ak][am] = av;
        }
        if (!TB) {
            *(float4*)&Bs[bk][bn] = bv;
        } else {
            Bs[bk + 0][bn] = bv.x; Bs[bk + 1][bn] = bv.y;
            Bs[bk + 2][bn] = bv.z; Bs[bk + 3][bn] = bv.w;
        }
        __syncthreads();

        #pragma unroll
        for (int k = 0; k < BK; k++) {
            float a[8], b[8];
            *(float4*)&a[0] = *(const float4*)&As[k][ty * 8];
            *(float4*)&a[4] = *(const float4*)&As[k][ty * 8 + 4];
            *(float4*)&b[0] = *(const float4*)&Bs[k][tx * 8];
            *(float4*)&b[4] = *(const float4*)&Bs[k][tx * 8 + 4];
            #pragma unroll
            for (int i = 0; i < 8; i++)
                #pragma unroll
                for (int j = 0; j < 8; j++)
                    acc[i][j] = fmaf(a[i], b[j], acc[i][j]);
        }
        __syncthreads();
    }

    #pragma unroll
    for (int i = 0; i < 8; i++) {
        float* crow = C + (ll)(m0 + ty * 8 + i) * N + n0 + tx * 8;
        #pragma unroll
        for (int j = 0; j < 8; j += 4) {
            float4 v = make_float4(acc[i][j], acc[i][j+1], acc[i][j+2], acc[i][j+3]);
            if (TH) { v.x = tanhf(v.x); v.y = tanhf(v.y); v.z = tanhf(v.z); v.w = tanhf(v.w); }
            *(float4*)(crow + j) = v;
        }
    }
}

// ---------------- fused residual-add + LayerNorm (rows of length S=1024) ----
__global__ __launch_bounds__(256) void add_ln_k(
    const float* __restrict__ x, const float* __restrict__ m,
    const float* __restrict__ g, const float* __restrict__ b,
    float* __restrict__ o)
{
    const int row = blockIdx.x;
    const ll off = (ll)row * SS;
    float v[4];
    float sum = 0.f, sq = 0.f;
    #pragma unroll
    for (int j = 0; j < 4; j++) {
        int i = threadIdx.x + j * 256;
        v[j] = x[off + i] + m[off + i];
        sum += v[j];
        sq  += v[j] * v[j];
    }
    #pragma unroll
    for (int o2 = 16; o2; o2 >>= 1) {
        sum += __shfl_xor_sync(0xffffffffu, sum, o2);
        sq  += __shfl_xor_sync(0xffffffffu, sq,  o2);
    }
    __shared__ float rs[8], rq[8];
    const int w = threadIdx.x >> 5, l = threadIdx.x & 31;
    if (l == 0) { rs[w] = sum; rq[w] = sq; }
    __syncthreads();
    if (w == 0) {
        float s2 = (l < 8) ? rs[l] : 0.f;
        float q2 = (l < 8) ? rq[l] : 0.f;
        #pragma unroll
        for (int o2 = 4; o2; o2 >>= 1) {
            s2 += __shfl_xor_sync(0xffffffffu, s2, o2);
            q2 += __shfl_xor_sync(0xffffffffu, q2, o2);
        }
        if (l == 0) { rs[0] = s2; rq[0] = q2; }
    }
    __syncthreads();
    const float mu  = rs[0] * (1.f / SS);
    const float var = rq[0] * (1.f / SS) - mu * mu;
    const float inv = rsqrtf(var + 1e-6f);
    #pragma unroll
    for (int j = 0; j < 4; j++) {
        int i = threadIdx.x + j * 256;
        o[off + i] = (v[j] - mu) * inv * g[i] + b[i];
    }
}

// ---------------- host orchestration ----------------------------------------
extern "C" void kernel_launch(void* const* d_in, const int* in_sizes, int n_in,
                              void* d_out, int out_size)
{
    const float* inp    = (const float*)d_in[0];
    const float* enc_k  = (const float*)d_in[1];
    const float* enc_v  = (const float*)d_in[2];
    const float* w_qkv1 = (const float*)d_in[3];
    const float* w_qkv2 = (const float*)d_in[4];
    const float* mh1_W1 = (const float*)d_in[5];
    const float* mh1_W2 = (const float*)d_in[6];
    const float* mh2_W1 = (const float*)d_in[7];
    const float* mh2_W2 = (const float*)d_in[8];
    const float* c1_w1  = (const float*)d_in[9];
    const float* c1_w2  = (const float*)d_in[10];
    const float* c2_w1  = (const float*)d_in[11];
    const float* c2_w2  = (const float*)d_in[12];
    const float* l1_w1  = (const float*)d_in[13];
    const float* l1_w2  = (const float*)d_in[14];
    const float* l2_w1  = (const float*)d_in[15];
    const float* l2_w2  = (const float*)d_in[16];
    const float* gamma  = (const float*)d_in[17];
    const float* beta   = (const float*)d_in[18];
    float* out = (float*)d_out;

    float *qkv, *z, *s, *bm, *att, *y, *mb, *hb, *x1, *x2;
    cudaGetSymbolAddress((void**)&qkv, g_qkv);
    cudaGetSymbolAddress((void**)&z,   g_z);
    cudaGetSymbolAddress((void**)&s,   g_s);
    cudaGetSymbolAddress((void**)&bm,  g_bm);
    cudaGetSymbolAddress((void**)&att, g_att);
    cudaGetSymbolAddress((void**)&y,   g_y);
    cudaGetSymbolAddress((void**)&mb,  g_m);
    cudaGetSymbolAddress((void**)&hb,  g_h);
    cudaGetSymbolAddress((void**)&x1,  g_x1);
    cudaGetSymbolAddress((void**)&x2,  g_x2);

    const ll DS = (ll)DD * SS;

    auto run_block = [&](const float* qp0, const float* qp1, const float* qp2,
                         const float* W1, const float* W2,
                         const float* cw1, const float* cw2) {
        const float* qp[3] = {qp0, qp1, qp2};
        for (int q = 0; q < 3; q++) {
            // z[h] = relu(qkv[q]) @ W1[h,q]^T      (D x MID, K=S), batch h
            gemm_k<false, true, true, false, false>
                <<<dim3(MIDD / BN, DD / BM, HH), 256>>>(
                    qp[q], W1 + (ll)q * MIDD * SS, z,
                    DD, MIDD, SS, 0, 3ll * MIDD * SS, (ll)DD * MIDD);
            // s[h,q] = relu(z[h]) @ W2[h,q]^T      (D x S, K=MID), batch h
            gemm_k<false, true, true, false, false>
                <<<dim3(SS / BN, DD / BM, HH), 256>>>(
                    z, W2 + (ll)q * SS * MIDD, s + (ll)q * DS,
                    DD, SS, MIDD, (ll)DD * MIDD, 3ll * SS * MIDD, 3ll * DS);
        }
        // b[h] = k[h]^T @ q[h]                      (S x S, K=D), batch h
        gemm_k<true, false, false, false, false>
            <<<dim3(SS / BN, SS / BM, HH), 256>>>(
                s + DS, s, bm, SS, SS, DD, 3ll * DS, 3ll * DS, (ll)SS * SS);
        // att[h] = v[h] @ b[h]                      (D x S, K=S), batch h
        gemm_k<false, false, false, false, false>
            <<<dim3(SS / BN, DD / BM, HH), 256>>>(
                s + 2ll * DS, bm, att, DD, SS, SS, 3ll * DS, (ll)SS * SS, DS);
        // y[s,m] = sum_c relu(cat[c,s]) * cw1[m,c]  (S x MID, K=H*D)
        gemm_k<true, true, true, false, false>
            <<<dim3(MIDD / BN, SS / BM, 1), 256>>>(
                att, cw1, y, SS, MIDD, HH * DD, 0, 0, 0);
        // m[d,s] = sum_m cw2[d,m] * relu(y[s,m])    (D x S, K=MID)
        gemm_k<false, true, false, true, false>
            <<<dim3(SS / BN, DD / BM, 1), 256>>>(
                cw2, y, mb, DD, SS, MIDD, 0, 0, 0);
    };

    // qkv1[q] = w_qkv1[q] @ inp                     (D x S, K=D), batch 3
    gemm_k<false, false, false, false, false>
        <<<dim3(SS / BN, DD / BM, 3), 256>>>(
            w_qkv1, inp, qkv, DD, SS, DD, (ll)DD * DD, 0, DS);

    run_block(qkv, qkv + DS, qkv + 2ll * DS, mh1_W1, mh1_W2, c1_w1, c1_w2);
    add_ln_k<<<DD, 256>>>(inp, mb, gamma, beta, hb);

    // q2 = w_qkv2[0] @ h1  -> reuse qkv slot 0
    gemm_k<false, false, false, false, false>
        <<<dim3(SS / BN, DD / BM, 1), 256>>>(
            w_qkv2, hb, qkv, DD, SS, DD, 0, 0, 0);

    run_block(qkv, enc_k, enc_v, mh2_W1, mh2_W2, c2_w1, c2_w2);
    add_ln_k<<<DD, 256>>>(inp, mb, gamma, beta, hb);

    // x1 = relu(h2) @ l1_w1^T                       (D x MID, K=S)
    gemm_k<false, true, true, false, false>
        <<<dim3(MIDD / BN, DD / BM, 1), 256>>>(hb, l1_w1, x1, DD, MIDD, SS, 0, 0, 0);
    // x2 = relu(x1) @ l1_w2^T                       (D x SOUT, K=MID)
    gemm_k<false, true, true, false, false>
        <<<dim3(SOUT / BN, DD / BM, 1), 256>>>(x1, l1_w2, x2, DD, SOUT, MIDD, 0, 0, 0);
    // y1 = relu(x2) @ l2_w1^T                       (D x MID, K=SOUT)
    gemm_k<false, true, true, false, false>
        <<<dim3(MIDD / BN, DD / BM, 1), 256>>>(x2, l2_w1, x1, DD, MIDD, SOUT, 0, 0, 0);
    // out = tanh(relu(y1) @ l2_w2^T)                (D x SOUT, K=MID)
    gemm_k<false, true, true, false, true>
        <<<dim3(SOUT / BN, DD / BM, 1), 256>>>(x1, l2_w2, out, DD, SOUT, MIDD, 0, 0, 0);
}